// round 13
// baseline (speedup 1.0000x reference)
#include <cuda_runtime.h>
#include <cuda_fp16.h>

#define BATCH 256
#define NROWS 256
#define MCOLS 256
#define DDIM  32
#define TPB   256                 // warps 0-3: producers, 4-7: DP consumers
#define NBLK  64                  // blocks of 4 columns
#define CITER 95                  // NBLK + 31 consumer iterations
#define RING  34                  // ring depth in blocks (>= 31 lane skew + slack)
#define LOG2E 1.4426950408889634f
#define BIGF  (1e8f * LOG2E)      // boundary in scaled (D*log2e) domain

__device__ float g_part[BATCH];
__device__ int   g_count;

typedef unsigned long long u64;

#define FMA_F32X2(d, a, b) \
    asm("fma.rn.f32x2 %0, %1, %2, %0;" : "+l"(d) : "l"(a), "l"(b))
#define UNPACK_F32X2(lo, hi, in) \
    asm("mov.b64 {%0, %1}, %2;" : "=f"(lo), "=f"(hi) : "l"(in))

__device__ __forceinline__ float ex2f(float x) {
    float r; asm("ex2.approx.f32 %0, %1;" : "=f"(r) : "f"(x)); return r;
}
__device__ __forceinline__ float lg2f(float x) {
    float r; asm("lg2.approx.f32 %0, %1;" : "=f"(r) : "f"(x)); return r;
}
__device__ __forceinline__ float softmin3s(float a, float b, float c) {
    float mn = fminf(fminf(a, b), c);
    float s  = ex2f(mn - a) + ex2f(mn - b) + ex2f(mn - c);
    return mn - lg2f(s);
}

// dynamic smem layout (bytes)
#define OFF_SY    0        // ulonglong2[8][256]  y chunk-transposed        32768
#define OFF_SYN   32768    // float[256] |y_j|^2  (reused for reduction)     1024
#define OFF_RING  33792    // [4 cons][RING slots][32 lanes x 16B f16 dist] 69632
#define OFF_PROG  103424   // int[4] producer progress + pad                  64
#define OFF_WRNG  103488   // u64[3][NBLK][4] dp handoff (tagged)           6144
#define OFF_CONS  109632   // int[4] consumer progress + pad                  64
#define SMEM_BYTES 109696

__global__ void __launch_bounds__(TPB, 2)
sdtw_kernel(const float* __restrict__ X, const float* __restrict__ Y,
            float* __restrict__ out) {
    extern __shared__ unsigned char sm[];
    ulonglong2*    sy16 = (ulonglong2*)(sm + OFF_SY);
    float*         syn  = (float*)(sm + OFF_SYN);
    volatile int*  prog = (volatile int*)(sm + OFF_PROG);
    volatile int*  cons = (volatile int*)(sm + OFF_CONS);
    __shared__ int islast;

    const int t    = threadIdx.x;
    const int lane = t & 31;
    const int wid  = t >> 5;
    const int b    = blockIdx.x;
    const float* xb = X + (size_t)b * NROWS * DDIM;
    const float* yb = Y + (size_t)b * MCOLS * DDIM;

    // ---- stage y chunk-transposed: sy16[c2][j] = float4 #c2 of y col j ----
    const ulonglong2* yb16 = (const ulonglong2*)yb;
    for (int k = t; k < MCOLS * 8; k += TPB) {
        int j = k >> 3, c2 = k & 7;
        sy16[c2 * 256 + j] = yb16[k];
    }
    {   // |y_j|^2
        const float4* row = (const float4*)(yb + t * DDIM);
        float acc = 0.f;
        #pragma unroll
        for (int c = 0; c < 8; c++) {
            float4 v = row[c];
            acc += v.x * v.x + v.y * v.y + v.z * v.z + v.w * v.w;
        }
        syn[t] = acc;
    }
    for (int k = t; k < 3 * NBLK * 4; k += TPB) ((u64*)(sm + OFF_WRNG))[k] = 0ull;
    if (t < 4) { ((int*)(sm + OFF_PROG))[t] = 0; ((int*)(sm + OFF_CONS))[t] = 0; }

    // producers pre-load their 2 x rows, packed f32x2
    u64 ax0[16], ax1[16];
    float xx0 = 0.f, xx1 = 0.f;
    if (wid < 4) {
        const ulonglong2* r0 = (const ulonglong2*)(xb + (size_t)(64 * wid + 2 * lane)     * DDIM);
        const ulonglong2* r1 = (const ulonglong2*)(xb + (size_t)(64 * wid + 2 * lane + 1) * DDIM);
        #pragma unroll
        for (int c2 = 0; c2 < 8; c2++) {
            ulonglong2 v0 = r0[c2], v1 = r1[c2];
            ax0[2*c2] = v0.x; ax0[2*c2+1] = v0.y;
            ax1[2*c2] = v1.x; ax1[2*c2+1] = v1.y;
            float a, bb;
            UNPACK_F32X2(a, bb, v0.x); xx0 += a*a + bb*bb;
            UNPACK_F32X2(a, bb, v0.y); xx0 += a*a + bb*bb;
            UNPACK_F32X2(a, bb, v1.x); xx1 += a*a + bb*bb;
            UNPACK_F32X2(a, bb, v1.y); xx1 += a*a + bb*bb;
        }
    }
    __syncthreads();

    if (wid < 4) {
        // ====== PRODUCER warp p: rows 64p+2l, +1; 4 cols per block ======
        const int p = wid;
        unsigned rbase;
        {   void* gp = (void*)(sm + OFF_RING + (size_t)p * RING * 512 + lane * 16);
            rbase = (unsigned)__cvta_generic_to_shared(gp); }
        unsigned paddr;
        {   void* gp = (void*)(prog + p);
            paddr = (unsigned)__cvta_generic_to_shared(gp); }
        volatile int* myc = cons + p;
        int slot = 0;
        #pragma unroll 1
        for (int j = 0; j < NBLK; j++) {
            if (j >= RING) {                        // backpressure: busy spin
                while (*myc < j - (RING - 1)) {}
            }
            const int c0 = 4 * j;
            u64 a00=0ull,a01=0ull,a02=0ull,a03=0ull;
            u64 a10=0ull,a11=0ull,a12=0ull,a13=0ull;
            #pragma unroll
            for (int c2 = 0; c2 < 8; c2++) {
                ulonglong2 y0 = sy16[c2 * 256 + c0];
                ulonglong2 y1 = sy16[c2 * 256 + c0 + 1];
                ulonglong2 y2 = sy16[c2 * 256 + c0 + 2];
                ulonglong2 y3 = sy16[c2 * 256 + c0 + 3];
                FMA_F32X2(a00, ax0[2*c2], y0.x); FMA_F32X2(a00, ax0[2*c2+1], y0.y);
                FMA_F32X2(a10, ax1[2*c2], y0.x); FMA_F32X2(a10, ax1[2*c2+1], y0.y);
                FMA_F32X2(a01, ax0[2*c2], y1.x); FMA_F32X2(a01, ax0[2*c2+1], y1.y);
                FMA_F32X2(a11, ax1[2*c2], y1.x); FMA_F32X2(a11, ax1[2*c2+1], y1.y);
                FMA_F32X2(a02, ax0[2*c2], y2.x); FMA_F32X2(a02, ax0[2*c2+1], y2.y);
                FMA_F32X2(a12, ax1[2*c2], y2.x); FMA_F32X2(a12, ax1[2*c2+1], y2.y);
                FMA_F32X2(a03, ax0[2*c2], y3.x); FMA_F32X2(a03, ax0[2*c2+1], y3.y);
                FMA_F32X2(a13, ax1[2*c2], y3.x); FMA_F32X2(a13, ax1[2*c2+1], y3.y);
            }
            float lo, hi;
            UNPACK_F32X2(lo, hi, a00); float d00 = lo + hi;
            UNPACK_F32X2(lo, hi, a10); float d10 = lo + hi;
            UNPACK_F32X2(lo, hi, a01); float d01 = lo + hi;
            UNPACK_F32X2(lo, hi, a11); float d11 = lo + hi;
            UNPACK_F32X2(lo, hi, a02); float d02 = lo + hi;
            UNPACK_F32X2(lo, hi, a12); float d12 = lo + hi;
            UNPACK_F32X2(lo, hi, a03); float d03 = lo + hi;
            UNPACK_F32X2(lo, hi, a13); float d13 = lo + hi;
            float y0n = syn[c0], y1n = syn[c0+1], y2n = syn[c0+2], y3n = syn[c0+3];
            d00 = fmaxf(fmaf(-2.f, d00, xx0 + y0n), 0.f) * LOG2E;
            d10 = fmaxf(fmaf(-2.f, d10, xx1 + y0n), 0.f) * LOG2E;
            d01 = fmaxf(fmaf(-2.f, d01, xx0 + y1n), 0.f) * LOG2E;
            d11 = fmaxf(fmaf(-2.f, d11, xx1 + y1n), 0.f) * LOG2E;
            d02 = fmaxf(fmaf(-2.f, d02, xx0 + y2n), 0.f) * LOG2E;
            d12 = fmaxf(fmaf(-2.f, d12, xx1 + y2n), 0.f) * LOG2E;
            d03 = fmaxf(fmaf(-2.f, d03, xx0 + y3n), 0.f) * LOG2E;
            d13 = fmaxf(fmaf(-2.f, d13, xx1 + y3n), 0.f) * LOG2E;
            __half2 h0 = __float22half2_rn(make_float2(d00, d10));
            __half2 h1 = __float22half2_rn(make_float2(d01, d11));
            __half2 h2 = __float22half2_rn(make_float2(d02, d12));
            __half2 h3 = __float22half2_rn(make_float2(d03, d13));
            unsigned u0 = *(unsigned*)&h0, u1 = *(unsigned*)&h1;
            unsigned u2 = *(unsigned*)&h2, u3 = *(unsigned*)&h3;
            unsigned a = rbase + (unsigned)(slot * 512);
            asm volatile("st.volatile.shared.v4.u32 [%0], {%1, %2, %3, %4};"
                         :: "r"(a), "r"(u0), "r"(u1), "r"(u2), "r"(u3));
            __syncwarp();
            if (lane == 0)
                asm volatile("st.volatile.shared.s32 [%0], %1;" :: "r"(paddr), "r"(j + 1));
            slot = (slot + 1 == RING) ? 0 : slot + 1;
        }
    } else {
        // ====== CONSUMER warp c: DP rows 64c+2l, +1; 2x4 tiles ======
        const int c = wid - 4;
        unsigned rbase;
        {   void* gp = (void*)(sm + OFF_RING + (size_t)c * RING * 512 + lane * 16);
            rbase = (unsigned)__cvta_generic_to_shared(gp); }
        volatile int* myprog = prog + c;
        unsigned caddr;
        {   void* gp = (void*)(cons + c);
            caddr = (unsigned)__cvta_generic_to_shared(gp); }
        u64* wrng = (u64*)(sm + OFF_WRNG);
        unsigned mywaddr = 0, upbase = 0;
        if (c < 3) {
            void* gp = (void*)(wrng + (size_t)c * NBLK * 4);
            mywaddr = (unsigned)__cvta_generic_to_shared(gp);
        }
        if (c > 0) {
            void* gp = (void*)(wrng + (size_t)(c - 1) * NBLK * 4);
            upbase = (unsigned)__cvta_generic_to_shared(gp);
        }

        float left0 = BIGF, left1 = BIGF;
        float tl = (c == 0 && lane == 0) ? 0.f : BIGF;
        float pv10 = BIGF, pv11 = BIGF, pv12 = BIGF, pv13 = BIGF;
        int slot = (RING - (lane % RING)) % RING;   // slot of bk = i - lane

        #pragma unroll 1
        for (int i = 0; i < CITER; i++) {
            float s10 = __shfl_up_sync(0xffffffffu, pv10, 1);
            float s11 = __shfl_up_sync(0xffffffffu, pv11, 1);
            float s12 = __shfl_up_sync(0xffffffffu, pv12, 1);
            float s13 = __shfl_up_sync(0xffffffffu, pv13, 1);

            {   // producer ready (first-try hit in steady state)
                const int need = (i + 1 < NBLK) ? i + 1 : NBLK;
                while (*myprog < need) {}
            }

            // own dist tile for block bk = i - lane (8 f16 in one LDS.128)
            unsigned a = rbase + (unsigned)(slot * 512);
            unsigned u0, u1, u2, u3;
            asm volatile("ld.volatile.shared.v4.u32 {%0, %1, %2, %3}, [%4];"
                         : "=r"(u0), "=r"(u1), "=r"(u2), "=r"(u3) : "r"(a));
            float2 f0 = __half22float2(*(__half2*)&u0);
            float2 f1 = __half22float2(*(__half2*)&u1);
            float2 f2 = __half22float2(*(__half2*)&u2);
            float2 f3 = __half22float2(*(__half2*)&u3);

            // cross-warp up quad: all lanes read + uniform spin, SEL into lane 0
            float up0 = BIGF, up1 = BIGF, up2 = BIGF, up3 = BIGF;
            if (c > 0) {
                const int ii = (i < NBLK) ? i : (NBLK - 1);
                const unsigned tag = (unsigned)(ii + 1);
                unsigned ua = upbase + (unsigned)(ii * 32);
                u64 w0, w1, w2, w3;
                asm volatile("ld.volatile.shared.v2.u64 {%0, %1}, [%2];"
                             : "=l"(w0), "=l"(w1) : "r"(ua));
                asm volatile("ld.volatile.shared.v2.u64 {%0, %1}, [%2];"
                             : "=l"(w2), "=l"(w3) : "r"(ua + 16));
                while ((unsigned)(w0 >> 32) != tag || (unsigned)(w1 >> 32) != tag ||
                       (unsigned)(w2 >> 32) != tag || (unsigned)(w3 >> 32) != tag) {
                    asm volatile("ld.volatile.shared.v2.u64 {%0, %1}, [%2];"
                                 : "=l"(w0), "=l"(w1) : "r"(ua));
                    asm volatile("ld.volatile.shared.v2.u64 {%0, %1}, [%2];"
                                 : "=l"(w2), "=l"(w3) : "r"(ua + 16));
                }
                up0 = __uint_as_float((unsigned)w0);
                up1 = __uint_as_float((unsigned)w1);
                up2 = __uint_as_float((unsigned)w2);
                up3 = __uint_as_float((unsigned)w3);
            }
            up0 = (lane == 0) ? up0 : s10;
            up1 = (lane == 0) ? up1 : s11;
            up2 = (lane == 0) ? up2 : s12;
            up3 = (lane == 0) ? up3 : s13;

            // 2x4 cell tile, chain depth 5
            float v00 = f0.x + softmin3s(up0, left0, tl);
            float v10 = f0.y + softmin3s(v00, left1, left0);
            float v01 = f1.x + softmin3s(up1, v00,   up0);
            float v11 = f1.y + softmin3s(v01, v10,   v00);
            float v02 = f2.x + softmin3s(up2, v01,   up1);
            float v12 = f2.y + softmin3s(v02, v11,   v01);
            float v03 = f3.x + softmin3s(up3, v02,   up2);
            float v13 = f3.y + softmin3s(v03, v12,   v02);

            const int bk = i - lane;
            const bool act = (bk >= 0) && (bk < NBLK);
            tl    = act ? up3 : tl;
            left0 = act ? v03 : left0;
            left1 = act ? v13 : left1;
            pv10  = act ? v10 : pv10;
            pv11  = act ? v11 : pv11;
            pv12  = act ? v12 : pv12;
            pv13  = act ? v13 : pv13;

            if (lane == 31) {   // free ring slots (consumed through bk = i-31)
                asm volatile("st.volatile.shared.s32 [%0], %1;"
                             :: "r"(caddr), "r"(i - 30));
            }
            if (act && lane == 31 && c < 3) {
                u64 tw = (u64)(unsigned)(bk + 1) << 32;
                unsigned wa = mywaddr + (unsigned)(bk * 32);
                u64 q0 = tw | (u64)__float_as_uint(v10);
                u64 q1 = tw | (u64)__float_as_uint(v11);
                u64 q2 = tw | (u64)__float_as_uint(v12);
                u64 q3 = tw | (u64)__float_as_uint(v13);
                asm volatile("st.volatile.shared.v2.u64 [%0], {%1, %2};"
                             :: "r"(wa), "l"(q0), "l"(q1));
                asm volatile("st.volatile.shared.v2.u64 [%0], {%1, %2};"
                             :: "r"(wa + 16), "l"(q2), "l"(q3));
            }
            if (c == 3 && lane == 31 && bk == NBLK - 1)
                g_part[b] = v13;                    // scaled D[N][M]

            slot = (slot + 1 == RING) ? 0 : slot + 1;
        }
    }

    // ---- fused grid reduction (last CTA); reuse syn[] as scratch ----
    __threadfence();
    __syncthreads();
    if (t == 0) islast = (atomicAdd(&g_count, 1) == BATCH - 1);
    __syncthreads();
    if (islast) {
        __threadfence();
        float* red = syn;
        red[t] = g_part[t];
        __syncthreads();
        #pragma unroll
        for (int off = TPB / 2; off > 0; off >>= 1) {
            if (t < off) red[t] += red[t + off];
            __syncthreads();
        }
        if (t == 0) {
            out[0] = red[0] * (1.0f / ((float)BATCH * LOG2E));
            g_count = 0;                            // reset for next graph replay
        }
    }
}

extern "C" void kernel_launch(void* const* d_in, const int* in_sizes, int n_in,
                              void* d_out, int out_size) {
    const float* x = (const float*)d_in[0];
    const float* y = (const float*)d_in[1];
    float* out = (float*)d_out;
    cudaFuncSetAttribute(sdtw_kernel, cudaFuncAttributeMaxDynamicSharedMemorySize,
                         SMEM_BYTES);
    sdtw_kernel<<<BATCH, TPB, SMEM_BYTES>>>(x, y, out);
}

// round 15
// speedup vs baseline: 1.1225x; 1.1225x over previous
#include <cuda_runtime.h>

#define BATCH 256
#define NROWS 256
#define MCOLS 256
#define DDIM  32
#define TPB   384                 // warps 0-7: producers (4/batch), 8-11: dual consumers
#define GRID  128                 // 2 batches per CTA
#define NBLK  128                 // blocks of 2 columns
#define CITER 159                 // NBLK + 31 consumer iterations
#define RING  34                  // ring depth in blocks
#define LOG2E 1.4426950408889634f
#define BIGF  (1e8f * LOG2E)      // boundary in scaled (D*log2e) domain

__device__ float g_part[BATCH];
__device__ int   g_count;

typedef unsigned long long u64;

#define FMA_F32X2(d, a, b) \
    asm("fma.rn.f32x2 %0, %1, %2, %0;" : "+l"(d) : "l"(a), "l"(b))
#define UNPACK_F32X2(lo, hi, in) \
    asm("mov.b64 {%0, %1}, %2;" : "=f"(lo), "=f"(hi) : "l"(in))

__device__ __forceinline__ float ex2f(float x) {
    float r; asm("ex2.approx.f32 %0, %1;" : "=f"(r) : "f"(x)); return r;
}
__device__ __forceinline__ float lg2f(float x) {
    float r; asm("lg2.approx.f32 %0, %1;" : "=f"(r) : "f"(x)); return r;
}
__device__ __forceinline__ float softmin3s(float a, float b, float c) {
    float mn = fminf(fminf(a, b), c);
    float s  = ex2f(mn - a) + ex2f(mn - b) + ex2f(mn - c);
    return mn - lg2f(s);
}

// dynamic smem layout (bytes)
#define OFF_SY    0        // ulonglong2[2][8][256] y chunk-transposed       65536
#define OFF_SYN   65536    // float[2][256] |y_j|^2 (reused for reduction)    2048
#define OFF_RING  67584    // [2 batches][4 cons][RING][32 lanes x 16B]     139264
#define OFF_PROG  206848   // int[8] producer progress (2p+q) + pad            64
#define OFF_WRNG  206912   // u64[2][3][NBLK][2] dp handoff (tagged)        12288
#define OFF_CONS  219200   // int[8] consumer progress (2p+q) + pad            64
#define SMEM_BYTES 219264
#define RING_B    69632    // per-batch ring bytes
#define RING_C    17408    // per-consumer ring bytes (RING*512)
#define WRNG_B    6144     // per-batch wrng bytes

__global__ void __launch_bounds__(TPB, 1)
sdtw_kernel(const float* __restrict__ X, const float* __restrict__ Y,
            float* __restrict__ out) {
    extern __shared__ unsigned char sm[];
    ulonglong2*    sy16 = (ulonglong2*)(sm + OFF_SY);
    float*         syn  = (float*)(sm + OFF_SYN);
    volatile int*  cons = (volatile int*)(sm + OFF_CONS);
    __shared__ int islast;

    const int t    = threadIdx.x;
    const int lane = t & 31;
    const int wid  = t >> 5;
    const int b    = blockIdx.x;          // batches 2b, 2b+1

    // ---- stage y for both batches, chunk-transposed ----
    for (int k = t; k < 2 * MCOLS * 8; k += TPB) {
        int q = k >> 11, rem = k & 2047;
        int j = rem >> 3, c2 = rem & 7;
        const ulonglong2* yq = (const ulonglong2*)(Y + (size_t)(2 * b + q) * MCOLS * DDIM);
        sy16[q * 2048 + c2 * 256 + j] = yq[rem];
    }
    for (int k = t; k < 2 * MCOLS; k += TPB) {   // |y_j|^2
        int q = k >> 8, j = k & 255;
        const float4* row = (const float4*)(Y + ((size_t)(2 * b + q) * MCOLS + j) * DDIM);
        float acc = 0.f;
        #pragma unroll
        for (int c = 0; c < 8; c++) {
            float4 v = row[c];
            acc += v.x * v.x + v.y * v.y + v.z * v.z + v.w * v.w;
        }
        syn[k] = acc;
    }
    for (int k = t; k < 2 * 3 * NBLK * 2; k += TPB) ((u64*)(sm + OFF_WRNG))[k] = 0ull;
    if (t < 8) { ((int*)(sm + OFF_PROG))[t] = 0; ((int*)(sm + OFF_CONS))[t] = 0; }

    // producers pre-load their 2 x rows (batch q, strip p), packed f32x2
    u64 ax0[16], ax1[16];
    float xx0 = 0.f, xx1 = 0.f;
    if (wid < 8) {
        const int q = wid >> 2, p = wid & 3;
        const float* xb = X + (size_t)(2 * b + q) * NROWS * DDIM;
        const ulonglong2* r0 = (const ulonglong2*)(xb + (size_t)(64 * p + 2 * lane)     * DDIM);
        const ulonglong2* r1 = (const ulonglong2*)(xb + (size_t)(64 * p + 2 * lane + 1) * DDIM);
        #pragma unroll
        for (int c2 = 0; c2 < 8; c2++) {
            ulonglong2 v0 = r0[c2], v1 = r1[c2];
            ax0[2*c2] = v0.x; ax0[2*c2+1] = v0.y;
            ax1[2*c2] = v1.x; ax1[2*c2+1] = v1.y;
            float a, bb;
            UNPACK_F32X2(a, bb, v0.x); xx0 += a*a + bb*bb;
            UNPACK_F32X2(a, bb, v0.y); xx0 += a*a + bb*bb;
            UNPACK_F32X2(a, bb, v1.x); xx1 += a*a + bb*bb;
            UNPACK_F32X2(a, bb, v1.y); xx1 += a*a + bb*bb;
        }
    }
    __syncthreads();

    if (wid < 8) {
        // ====== PRODUCER (batch q, strip p): rows 64p+2l, +1; 2 cols/block ======
        const int q = wid >> 2, p = wid & 3;
        const ulonglong2* syq = sy16 + q * 2048;
        const float*      snq = syn  + q * 256;
        unsigned rbase;
        {   void* gp = (void*)(sm + OFF_RING + q * RING_B + p * RING_C + lane * 16);
            rbase = (unsigned)__cvta_generic_to_shared(gp); }
        unsigned paddr;
        {   void* gp = (void*)(sm + OFF_PROG + (2 * p + q) * 4);
            paddr = (unsigned)__cvta_generic_to_shared(gp); }
        volatile int* myc = cons + (2 * p + q);
        int slot = 0;
        #pragma unroll 1
        for (int j = 0; j < NBLK; j++) {
            if (j >= RING) {                        // backpressure: busy spin
                while (*myc < j - (RING - 1)) {}
            }
            const int c0 = 2 * j;
            u64 a00 = 0ull, a01 = 0ull, a10 = 0ull, a11 = 0ull;
            #pragma unroll
            for (int c2 = 0; c2 < 8; c2++) {
                ulonglong2 y0 = syq[c2 * 256 + c0];       // broadcast LDS.128
                ulonglong2 y1 = syq[c2 * 256 + c0 + 1];
                FMA_F32X2(a00, ax0[2*c2], y0.x); FMA_F32X2(a00, ax0[2*c2+1], y0.y);
                FMA_F32X2(a10, ax1[2*c2], y0.x); FMA_F32X2(a10, ax1[2*c2+1], y0.y);
                FMA_F32X2(a01, ax0[2*c2], y1.x); FMA_F32X2(a01, ax0[2*c2+1], y1.y);
                FMA_F32X2(a11, ax1[2*c2], y1.x); FMA_F32X2(a11, ax1[2*c2+1], y1.y);
            }
            float lo, hi;
            UNPACK_F32X2(lo, hi, a00); float d00 = lo + hi;
            UNPACK_F32X2(lo, hi, a10); float d10 = lo + hi;
            UNPACK_F32X2(lo, hi, a01); float d01 = lo + hi;
            UNPACK_F32X2(lo, hi, a11); float d11 = lo + hi;
            float yn0 = snq[c0], yn1 = snq[c0 + 1];
            d00 = fmaxf(fmaf(-2.f, d00, xx0 + yn0), 0.f) * LOG2E;
            d10 = fmaxf(fmaf(-2.f, d10, xx1 + yn0), 0.f) * LOG2E;
            d01 = fmaxf(fmaf(-2.f, d01, xx0 + yn1), 0.f) * LOG2E;
            d11 = fmaxf(fmaf(-2.f, d11, xx1 + yn1), 0.f) * LOG2E;
            unsigned a = rbase + (unsigned)(slot * 512);
            // component order: (r0c0, r1c0, r0c1, r1c1)
            asm volatile("st.volatile.shared.v4.f32 [%0], {%1, %2, %3, %4};"
                         :: "r"(a), "f"(d00), "f"(d10), "f"(d01), "f"(d11));
            __syncwarp();
            if (lane == 0)
                asm volatile("st.volatile.shared.s32 [%0], %1;" :: "r"(paddr), "r"(j + 1));
            slot = (slot + 1 == RING) ? 0 : slot + 1;
        }
    } else {
        // ====== CONSUMER warp c: strips of BOTH batches, interleaved chains ======
        const int c = wid - 8;
        unsigned rbA, rbB;
        {   void* gp = (void*)(sm + OFF_RING + 0 * RING_B + c * RING_C + lane * 16);
            rbA = (unsigned)__cvta_generic_to_shared(gp); }
        {   void* gp = (void*)(sm + OFF_RING + 1 * RING_B + c * RING_C + lane * 16);
            rbB = (unsigned)__cvta_generic_to_shared(gp); }
        unsigned paddr2, caddr2;
        {   void* gp = (void*)(sm + OFF_PROG + 2 * c * 4);
            paddr2 = (unsigned)__cvta_generic_to_shared(gp); }
        {   void* gp = (void*)(sm + OFF_CONS + 2 * c * 4);
            caddr2 = (unsigned)__cvta_generic_to_shared(gp); }
        u64* wrA = (u64*)(sm + OFF_WRNG);
        u64* wrB = (u64*)(sm + OFF_WRNG + WRNG_B);
        volatile u64* mywA = wrA + (size_t)c * NBLK * 2;
        volatile u64* mywB = wrB + (size_t)c * NBLK * 2;
        unsigned upA = 0, upB = 0;
        if (c > 0) {
            void* g1 = (void*)(wrA + (size_t)(c - 1) * NBLK * 2);
            upA = (unsigned)__cvta_generic_to_shared(g1);
            void* g2 = (void*)(wrB + (size_t)(c - 1) * NBLK * 2);
            upB = (unsigned)__cvta_generic_to_shared(g2);
        }

        float l0A = BIGF, l1A = BIGF, tlA = (c == 0 && lane == 0) ? 0.f : BIGF;
        float p10A = BIGF, p11A = BIGF;
        float l0B = BIGF, l1B = BIGF, tlB = (c == 0 && lane == 0) ? 0.f : BIGF;
        float p10B = BIGF, p11B = BIGF;
        int slot = (RING - (lane % RING)) % RING;   // slot of bk = i - lane

        #pragma unroll 1
        for (int i = 0; i < CITER; i++) {
            float s10A = __shfl_up_sync(0xffffffffu, p10A, 1);
            float s11A = __shfl_up_sync(0xffffffffu, p11A, 1);
            float s10B = __shfl_up_sync(0xffffffffu, p10B, 1);
            float s11B = __shfl_up_sync(0xffffffffu, p11B, 1);

            {   // both batches' producers ready (one v2 poll)
                const int need = (i + 1 < NBLK) ? i + 1 : NBLK;
                int pa, pb;
                asm volatile("ld.volatile.shared.v2.u32 {%0, %1}, [%2];"
                             : "=r"(pa), "=r"(pb) : "r"(paddr2));
                while (pa < need || pb < need) {
                    asm volatile("ld.volatile.shared.v2.u32 {%0, %1}, [%2];"
                                 : "=r"(pa), "=r"(pb) : "r"(paddr2));
                }
            }

            unsigned aA = rbA + (unsigned)(slot * 512);
            unsigned aB = rbB + (unsigned)(slot * 512);
            // components: dx=r0c0, dy=r1c0, dz=r0c1, dw=r1c1
            float dxA, dyA, dzA, dwA, dxB, dyB, dzB, dwB;
            asm volatile("ld.volatile.shared.v4.f32 {%0, %1, %2, %3}, [%4];"
                         : "=f"(dxA), "=f"(dyA), "=f"(dzA), "=f"(dwA) : "r"(aA));
            asm volatile("ld.volatile.shared.v4.f32 {%0, %1, %2, %3}, [%4];"
                         : "=f"(dxB), "=f"(dyB), "=f"(dzB), "=f"(dwB) : "r"(aB));

            // cross-warp up pairs (all lanes read + uniform spin, SEL into lane 0)
            float u0A = BIGF, u1A = BIGF, u0B = BIGF, u1B = BIGF;
            if (c > 0) {
                const int ii = (i < NBLK) ? i : (NBLK - 1);
                const unsigned tag = (unsigned)(ii + 1);
                unsigned uaA = upA + (unsigned)(ii * 16);
                unsigned uaB = upB + (unsigned)(ii * 16);
                u64 w0, w1;
                asm volatile("ld.volatile.shared.v2.u64 {%0, %1}, [%2];"
                             : "=l"(w0), "=l"(w1) : "r"(uaA));
                while ((unsigned)(w0 >> 32) != tag || (unsigned)(w1 >> 32) != tag) {
                    asm volatile("ld.volatile.shared.v2.u64 {%0, %1}, [%2];"
                                 : "=l"(w0), "=l"(w1) : "r"(uaA));
                }
                u0A = __uint_as_float((unsigned)w0);
                u1A = __uint_as_float((unsigned)w1);
                asm volatile("ld.volatile.shared.v2.u64 {%0, %1}, [%2];"
                             : "=l"(w0), "=l"(w1) : "r"(uaB));
                while ((unsigned)(w0 >> 32) != tag || (unsigned)(w1 >> 32) != tag) {
                    asm volatile("ld.volatile.shared.v2.u64 {%0, %1}, [%2];"
                                 : "=l"(w0), "=l"(w1) : "r"(uaB));
                }
                u0B = __uint_as_float((unsigned)w0);
                u1B = __uint_as_float((unsigned)w1);
            }
            u0A = (lane == 0) ? u0A : s10A;
            u1A = (lane == 0) ? u1A : s11A;
            u0B = (lane == 0) ? u0B : s10B;
            u1B = (lane == 0) ? u1B : s11B;

            // two independent 2x2 tiles (chains interleave in the scheduler)
            // v00: (r0c0), v10: (r1c0)=dy, v01: (r0c1)=dz, v11: (r1c1)=dw
            float v00A = dxA + softmin3s(u0A, l0A, tlA);
            float v00B = dxB + softmin3s(u0B, l0B, tlB);
            float v10A = dyA + softmin3s(v00A, l1A, l0A);
            float v10B = dyB + softmin3s(v00B, l1B, l0B);
            float v01A = dzA + softmin3s(u1A, v00A, u0A);
            float v01B = dzB + softmin3s(u1B, v00B, u0B);
            float v11A = dwA + softmin3s(v01A, v10A, v00A);
            float v11B = dwB + softmin3s(v01B, v10B, v00B);

            const int bk = i - lane;
            const bool act = (bk >= 0) && (bk < NBLK);
            tlA  = act ? u1A  : tlA;  l0A = act ? v01A : l0A;  l1A = act ? v11A : l1A;
            p10A = act ? v10A : p10A; p11A = act ? v11A : p11A;
            tlB  = act ? u1B  : tlB;  l0B = act ? v01B : l0B;  l1B = act ? v11B : l1B;
            p10B = act ? v10B : p10B; p11B = act ? v11B : p11B;

            if (lane == 31) {   // free ring slots for both batches (one v2 store)
                int cv = i - 30;
                asm volatile("st.volatile.shared.v2.u32 [%0], {%1, %2};"
                             :: "r"(caddr2), "r"(cv), "r"(cv));
            }
            if (act && lane == 31 && c < 3) {
                u64 tw = (u64)(unsigned)(bk + 1) << 32;
                mywA[bk * 2 + 0] = tw | (u64)__float_as_uint(v10A);
                mywA[bk * 2 + 1] = tw | (u64)__float_as_uint(v11A);
                mywB[bk * 2 + 0] = tw | (u64)__float_as_uint(v10B);
                mywB[bk * 2 + 1] = tw | (u64)__float_as_uint(v11B);
            }
            if (c == 3 && lane == 31 && bk == NBLK - 1) {
                g_part[2 * b]     = v11A;           // scaled D[N][M], batch A
                g_part[2 * b + 1] = v11B;           // batch B
            }

            slot = (slot + 1 == RING) ? 0 : slot + 1;
        }
    }

    // ---- fused grid reduction (last CTA); reuse syn[] as scratch ----
    __threadfence();
    __syncthreads();
    if (t == 0) islast = (atomicAdd(&g_count, 1) == GRID - 1);
    __syncthreads();
    if (islast) {
        __threadfence();
        float* red = syn;
        if (t < BATCH) red[t] = g_part[t];
        __syncthreads();
        #pragma unroll
        for (int off = BATCH / 2; off > 0; off >>= 1) {
            if (t < off) red[t] += red[t + off];
            __syncthreads();
        }
        if (t == 0) {
            out[0] = red[0] * (1.0f / ((float)BATCH * LOG2E));
            g_count = 0;                            // reset for next graph replay
        }
    }
}

extern "C" void kernel_launch(void* const* d_in, const int* in_sizes, int n_in,
                              void* d_out, int out_size) {
    const float* x = (const float*)d_in[0];
    const float* y = (const float*)d_in[1];
    float* out = (float*)d_out;
    cudaFuncSetAttribute(sdtw_kernel, cudaFuncAttributeMaxDynamicSharedMemorySize,
                         SMEM_BYTES);
    sdtw_kernel<<<GRID, TPB, SMEM_BYTES>>>(x, y, out);
}

// round 16
// speedup vs baseline: 1.1249x; 1.0021x over previous
#include <cuda_runtime.h>

#define BATCH 256
#define NROWS 256
#define MCOLS 256
#define DDIM  32
#define TPB   384                 // warps 0-7: producers (4/batch), 8-11: dual consumers
#define GRID  128                 // 2 batches per CTA
#define NBLK  128                 // blocks of 2 columns
#define CITER 159                 // NBLK + 31 consumer iterations
#define RING  34                  // ring depth in blocks
#define LOG2E 1.4426950408889634f
#define BIGF  (1e8f * LOG2E)      // boundary in scaled (D*log2e) domain

__device__ float g_part[BATCH];
__device__ int   g_count;

typedef unsigned long long u64;

#define FMA_F32X2(d, a, b) \
    asm("fma.rn.f32x2 %0, %1, %2, %0;" : "+l"(d) : "l"(a), "l"(b))
#define UNPACK_F32X2(lo, hi, in) \
    asm("mov.b64 {%0, %1}, %2;" : "=f"(lo), "=f"(hi) : "l"(in))

__device__ __forceinline__ float ex2f(float x) {
    float r; asm("ex2.approx.f32 %0, %1;" : "=f"(r) : "f"(x)); return r;
}
__device__ __forceinline__ float lg2f(float x) {
    float r; asm("lg2.approx.f32 %0, %1;" : "=f"(r) : "f"(x)); return r;
}
__device__ __forceinline__ float softmin3s(float a, float b, float c) {
    float mn = fminf(fminf(a, b), c);
    float s  = ex2f(mn - a) + ex2f(mn - b) + ex2f(mn - c);
    return mn - lg2f(s);
}

// dynamic smem layout (bytes)
#define OFF_SY    0        // ulonglong2[2][8][256] y chunk-transposed       65536
#define OFF_SYN   65536    // float[2][256] |y_j|^2 (reused for reduction)    2048
#define OFF_RING  67584    // [2 batches][4 cons][RING][32 lanes x 16B]     139264
#define OFF_PROG  206848   // int[8] producer progress (2p+q) + pad            64
#define OFF_WRNG  206912   // u64[2][3][NBLK][2] dp handoff (tagged)        12288
#define OFF_CONS  219200   // int[8] consumer progress (2p+q) + pad            64
#define SMEM_BYTES 219264
#define RING_B    69632    // per-batch ring bytes
#define RING_C    17408    // per-consumer ring bytes (RING*512)
#define WRNG_B    6144     // per-batch wrng bytes

__global__ void __launch_bounds__(TPB, 1)
sdtw_kernel(const float* __restrict__ X, const float* __restrict__ Y,
            float* __restrict__ out) {
    extern __shared__ unsigned char sm[];
    ulonglong2*    sy16 = (ulonglong2*)(sm + OFF_SY);
    float*         syn  = (float*)(sm + OFF_SYN);
    volatile int*  cons = (volatile int*)(sm + OFF_CONS);
    __shared__ int islast;

    const int t    = threadIdx.x;
    const int lane = t & 31;
    const int wid  = t >> 5;
    const int b    = blockIdx.x;          // batches 2b, 2b+1

    // ---- stage y for both batches, chunk-transposed ----
    for (int k = t; k < 2 * MCOLS * 8; k += TPB) {
        int q = k >> 11, rem = k & 2047;
        int j = rem >> 3, c2 = rem & 7;
        const ulonglong2* yq = (const ulonglong2*)(Y + (size_t)(2 * b + q) * MCOLS * DDIM);
        sy16[q * 2048 + c2 * 256 + j] = yq[rem];
    }
    for (int k = t; k < 2 * MCOLS; k += TPB) {   // |y_j|^2
        int q = k >> 8, j = k & 255;
        const float4* row = (const float4*)(Y + ((size_t)(2 * b + q) * MCOLS + j) * DDIM);
        float acc = 0.f;
        #pragma unroll
        for (int c = 0; c < 8; c++) {
            float4 v = row[c];
            acc += v.x * v.x + v.y * v.y + v.z * v.z + v.w * v.w;
        }
        syn[k] = acc;
    }
    for (int k = t; k < 2 * 3 * NBLK * 2; k += TPB) ((u64*)(sm + OFF_WRNG))[k] = 0ull;
    if (t < 8) { ((int*)(sm + OFF_PROG))[t] = 0; ((int*)(sm + OFF_CONS))[t] = 0; }

    // producers pre-load their 2 x rows (batch q, strip p), packed f32x2
    u64 ax0[16], ax1[16];
    float xx0 = 0.f, xx1 = 0.f;
    if (wid < 8) {
        const int q = wid >> 2, p = wid & 3;
        const float* xb = X + (size_t)(2 * b + q) * NROWS * DDIM;
        const ulonglong2* r0 = (const ulonglong2*)(xb + (size_t)(64 * p + 2 * lane)     * DDIM);
        const ulonglong2* r1 = (const ulonglong2*)(xb + (size_t)(64 * p + 2 * lane + 1) * DDIM);
        #pragma unroll
        for (int c2 = 0; c2 < 8; c2++) {
            ulonglong2 v0 = r0[c2], v1 = r1[c2];
            ax0[2*c2] = v0.x; ax0[2*c2+1] = v0.y;
            ax1[2*c2] = v1.x; ax1[2*c2+1] = v1.y;
            float a, bb;
            UNPACK_F32X2(a, bb, v0.x); xx0 += a*a + bb*bb;
            UNPACK_F32X2(a, bb, v0.y); xx0 += a*a + bb*bb;
            UNPACK_F32X2(a, bb, v1.x); xx1 += a*a + bb*bb;
            UNPACK_F32X2(a, bb, v1.y); xx1 += a*a + bb*bb;
        }
    }
    __syncthreads();

    if (wid < 8) {
        // ====== PRODUCER (batch q, strip p): rows 64p+2l, +1; 2 cols/block ======
        const int q = wid >> 2, p = wid & 3;
        const ulonglong2* syq = sy16 + q * 2048;
        const float*      snq = syn  + q * 256;
        unsigned rbase;
        {   void* gp = (void*)(sm + OFF_RING + q * RING_B + p * RING_C + lane * 16);
            rbase = (unsigned)__cvta_generic_to_shared(gp); }
        unsigned paddr;
        {   void* gp = (void*)(sm + OFF_PROG + (2 * p + q) * 4);
            paddr = (unsigned)__cvta_generic_to_shared(gp); }
        volatile int* myc = cons + (2 * p + q);
        int slot = 0;
        #pragma unroll 1
        for (int j = 0; j < NBLK; j++) {
            if (j >= RING) {                        // backpressure: busy spin
                while (*myc < j - (RING - 1)) {}
            }
            const int c0 = 2 * j;
            u64 a00 = 0ull, a01 = 0ull, a10 = 0ull, a11 = 0ull;
            #pragma unroll
            for (int c2 = 0; c2 < 8; c2++) {
                ulonglong2 y0 = syq[c2 * 256 + c0];       // broadcast LDS.128
                ulonglong2 y1 = syq[c2 * 256 + c0 + 1];
                FMA_F32X2(a00, ax0[2*c2], y0.x); FMA_F32X2(a00, ax0[2*c2+1], y0.y);
                FMA_F32X2(a10, ax1[2*c2], y0.x); FMA_F32X2(a10, ax1[2*c2+1], y0.y);
                FMA_F32X2(a01, ax0[2*c2], y1.x); FMA_F32X2(a01, ax0[2*c2+1], y1.y);
                FMA_F32X2(a11, ax1[2*c2], y1.x); FMA_F32X2(a11, ax1[2*c2+1], y1.y);
            }
            float lo, hi;
            UNPACK_F32X2(lo, hi, a00); float d00 = lo + hi;
            UNPACK_F32X2(lo, hi, a10); float d10 = lo + hi;
            UNPACK_F32X2(lo, hi, a01); float d01 = lo + hi;
            UNPACK_F32X2(lo, hi, a11); float d11 = lo + hi;
            float yn0 = snq[c0], yn1 = snq[c0 + 1];
            d00 = fmaxf(fmaf(-2.f, d00, xx0 + yn0), 0.f) * LOG2E;
            d10 = fmaxf(fmaf(-2.f, d10, xx1 + yn0), 0.f) * LOG2E;
            d01 = fmaxf(fmaf(-2.f, d01, xx0 + yn1), 0.f) * LOG2E;
            d11 = fmaxf(fmaf(-2.f, d11, xx1 + yn1), 0.f) * LOG2E;
            unsigned a = rbase + (unsigned)(slot * 512);
            // component order: (r0c0, r1c0, r0c1, r1c1)
            asm volatile("st.volatile.shared.v4.f32 [%0], {%1, %2, %3, %4};"
                         :: "r"(a), "f"(d00), "f"(d10), "f"(d01), "f"(d11));
            __syncwarp();
            if (lane == 0)
                asm volatile("st.volatile.shared.s32 [%0], %1;" :: "r"(paddr), "r"(j + 1));
            slot = (slot + 1 == RING) ? 0 : slot + 1;
        }
    } else {
        // ====== CONSUMER warp c: strips of BOTH batches, interleaved chains ======
        const int c = wid - 8;
        unsigned rbA, rbB;
        {   void* gp = (void*)(sm + OFF_RING + 0 * RING_B + c * RING_C + lane * 16);
            rbA = (unsigned)__cvta_generic_to_shared(gp); }
        {   void* gp = (void*)(sm + OFF_RING + 1 * RING_B + c * RING_C + lane * 16);
            rbB = (unsigned)__cvta_generic_to_shared(gp); }
        unsigned paddr2, caddr2;
        {   void* gp = (void*)(sm + OFF_PROG + 2 * c * 4);
            paddr2 = (unsigned)__cvta_generic_to_shared(gp); }
        {   void* gp = (void*)(sm + OFF_CONS + 2 * c * 4);
            caddr2 = (unsigned)__cvta_generic_to_shared(gp); }
        u64* wrA = (u64*)(sm + OFF_WRNG);
        u64* wrB = (u64*)(sm + OFF_WRNG + WRNG_B);
        volatile u64* mywA = wrA + (size_t)c * NBLK * 2;
        volatile u64* mywB = wrB + (size_t)c * NBLK * 2;
        unsigned upA = 0, upB = 0;
        if (c > 0) {
            void* g1 = (void*)(wrA + (size_t)(c - 1) * NBLK * 2);
            upA = (unsigned)__cvta_generic_to_shared(g1);
            void* g2 = (void*)(wrB + (size_t)(c - 1) * NBLK * 2);
            upB = (unsigned)__cvta_generic_to_shared(g2);
        }

        float l0A = BIGF, l1A = BIGF, tlA = (c == 0 && lane == 0) ? 0.f : BIGF;
        float p10A = BIGF, p11A = BIGF;
        float l0B = BIGF, l1B = BIGF, tlB = (c == 0 && lane == 0) ? 0.f : BIGF;
        float p10B = BIGF, p11B = BIGF;
        int slot = (RING - (lane % RING)) % RING;   // slot of bk = i - lane

        #pragma unroll 1
        for (int i = 0; i < CITER; i++) {
            float s10A = __shfl_up_sync(0xffffffffu, p10A, 1);
            float s11A = __shfl_up_sync(0xffffffffu, p11A, 1);
            float s10B = __shfl_up_sync(0xffffffffu, p10B, 1);
            float s11B = __shfl_up_sync(0xffffffffu, p11B, 1);

            {   // both batches' producers ready (one v2 poll)
                const int need = (i + 1 < NBLK) ? i + 1 : NBLK;
                int pa, pb;
                asm volatile("ld.volatile.shared.v2.u32 {%0, %1}, [%2];"
                             : "=r"(pa), "=r"(pb) : "r"(paddr2));
                while (pa < need || pb < need) {
                    asm volatile("ld.volatile.shared.v2.u32 {%0, %1}, [%2];"
                                 : "=r"(pa), "=r"(pb) : "r"(paddr2));
                }
            }

            unsigned aA = rbA + (unsigned)(slot * 512);
            unsigned aB = rbB + (unsigned)(slot * 512);
            // components: dx=r0c0, dy=r1c0, dz=r0c1, dw=r1c1
            float dxA, dyA, dzA, dwA, dxB, dyB, dzB, dwB;
            asm volatile("ld.volatile.shared.v4.f32 {%0, %1, %2, %3}, [%4];"
                         : "=f"(dxA), "=f"(dyA), "=f"(dzA), "=f"(dwA) : "r"(aA));
            asm volatile("ld.volatile.shared.v4.f32 {%0, %1, %2, %3}, [%4];"
                         : "=f"(dxB), "=f"(dyB), "=f"(dzB), "=f"(dwB) : "r"(aB));

            // cross-warp up pairs (all lanes read + uniform spin, SEL into lane 0)
            float u0A = BIGF, u1A = BIGF, u0B = BIGF, u1B = BIGF;
            if (c > 0) {
                const int ii = (i < NBLK) ? i : (NBLK - 1);
                const unsigned tag = (unsigned)(ii + 1);
                unsigned uaA = upA + (unsigned)(ii * 16);
                unsigned uaB = upB + (unsigned)(ii * 16);
                u64 w0, w1;
                asm volatile("ld.volatile.shared.v2.u64 {%0, %1}, [%2];"
                             : "=l"(w0), "=l"(w1) : "r"(uaA));
                while ((unsigned)(w0 >> 32) != tag || (unsigned)(w1 >> 32) != tag) {
                    asm volatile("ld.volatile.shared.v2.u64 {%0, %1}, [%2];"
                                 : "=l"(w0), "=l"(w1) : "r"(uaA));
                }
                u0A = __uint_as_float((unsigned)w0);
                u1A = __uint_as_float((unsigned)w1);
                asm volatile("ld.volatile.shared.v2.u64 {%0, %1}, [%2];"
                             : "=l"(w0), "=l"(w1) : "r"(uaB));
                while ((unsigned)(w0 >> 32) != tag || (unsigned)(w1 >> 32) != tag) {
                    asm volatile("ld.volatile.shared.v2.u64 {%0, %1}, [%2];"
                                 : "=l"(w0), "=l"(w1) : "r"(uaB));
                }
                u0B = __uint_as_float((unsigned)w0);
                u1B = __uint_as_float((unsigned)w1);
            }
            u0A = (lane == 0) ? u0A : s10A;
            u1A = (lane == 0) ? u1A : s11A;
            u0B = (lane == 0) ? u0B : s10B;
            u1B = (lane == 0) ? u1B : s11B;

            // two independent 2x2 tiles (chains interleave in the scheduler)
            // v00: (r0c0), v10: (r1c0)=dy, v01: (r0c1)=dz, v11: (r1c1)=dw
            float v00A = dxA + softmin3s(u0A, l0A, tlA);
            float v00B = dxB + softmin3s(u0B, l0B, tlB);
            float v10A = dyA + softmin3s(v00A, l1A, l0A);
            float v10B = dyB + softmin3s(v00B, l1B, l0B);
            float v01A = dzA + softmin3s(u1A, v00A, u0A);
            float v01B = dzB + softmin3s(u1B, v00B, u0B);
            float v11A = dwA + softmin3s(v01A, v10A, v00A);
            float v11B = dwB + softmin3s(v01B, v10B, v00B);

            const int bk = i - lane;
            const bool act = (bk >= 0) && (bk < NBLK);
            tlA  = act ? u1A  : tlA;  l0A = act ? v01A : l0A;  l1A = act ? v11A : l1A;
            p10A = act ? v10A : p10A; p11A = act ? v11A : p11A;
            tlB  = act ? u1B  : tlB;  l0B = act ? v01B : l0B;  l1B = act ? v11B : l1B;
            p10B = act ? v10B : p10B; p11B = act ? v11B : p11B;

            if (lane == 31) {   // free ring slots for both batches (one v2 store)
                int cv = i - 30;
                asm volatile("st.volatile.shared.v2.u32 [%0], {%1, %2};"
                             :: "r"(caddr2), "r"(cv), "r"(cv));
            }
            if (act && lane == 31 && c < 3) {
                u64 tw = (u64)(unsigned)(bk + 1) << 32;
                mywA[bk * 2 + 0] = tw | (u64)__float_as_uint(v10A);
                mywA[bk * 2 + 1] = tw | (u64)__float_as_uint(v11A);
                mywB[bk * 2 + 0] = tw | (u64)__float_as_uint(v10B);
                mywB[bk * 2 + 1] = tw | (u64)__float_as_uint(v11B);
            }
            if (c == 3 && lane == 31 && bk == NBLK - 1) {
                g_part[2 * b]     = v11A;           // scaled D[N][M], batch A
                g_part[2 * b + 1] = v11B;           // batch B
            }

            slot = (slot + 1 == RING) ? 0 : slot + 1;
        }
    }

    // ---- fused grid reduction (last CTA); reuse syn[] as scratch ----
    __threadfence();
    __syncthreads();
    if (t == 0) islast = (atomicAdd(&g_count, 1) == GRID - 1);
    __syncthreads();
    if (islast) {
        __threadfence();
        float* red = syn;
        if (t < BATCH) red[t] = g_part[t];
        __syncthreads();
        #pragma unroll
        for (int off = BATCH / 2; off > 0; off >>= 1) {
            if (t < off) red[t] += red[t + off];
            __syncthreads();
        }
        if (t == 0) {
            out[0] = red[0] * (1.0f / ((float)BATCH * LOG2E));
            g_count = 0;                            // reset for next graph replay
        }
    }
}

extern "C" void kernel_launch(void* const* d_in, const int* in_sizes, int n_in,
                              void* d_out, int out_size) {
    const float* x = (const float*)d_in[0];
    const float* y = (const float*)d_in[1];
    float* out = (float*)d_out;
    cudaFuncSetAttribute(sdtw_kernel, cudaFuncAttributeMaxDynamicSharedMemorySize,
                         SMEM_BYTES);
    sdtw_kernel<<<GRID, TPB, SMEM_BYTES>>>(x, y, out);
}

// round 17
// speedup vs baseline: 1.1605x; 1.0316x over previous
#include <cuda_runtime.h>
#include <cuda_fp16.h>

#define BATCH 256
#define NROWS 256
#define MCOLS 256
#define DDIM  32
#define TPB   256                 // warps 0-3: producers, 4-7: DP consumers
#define NBLK  128                 // blocks of 2 columns
#define CITER 159                 // NBLK + 31 consumer iterations
#define RING  64                  // ring depth in blocks (fp16 entries)
#define SLACKCAP 62               // producer may lead consumed-counter by this
#define LOG2E 1.4426950408889634f
#define NEG2L (-2.0f * LOG2E)
#define BIGF  (1e8f * LOG2E)      // boundary in scaled (D*log2e) domain

__device__ float g_part[BATCH];
__device__ int   g_count;

typedef unsigned long long u64;

#define FMA_F32X2(d, a, b) \
    asm("fma.rn.f32x2 %0, %1, %2, %0;" : "+l"(d) : "l"(a), "l"(b))
#define UNPACK_F32X2(lo, hi, in) \
    asm("mov.b64 {%0, %1}, %2;" : "=f"(lo), "=f"(hi) : "l"(in))

__device__ __forceinline__ float ex2f(float x) {
    float r; asm("ex2.approx.f32 %0, %1;" : "=f"(r) : "f"(x)); return r;
}
__device__ __forceinline__ float lg2f(float x) {
    float r; asm("lg2.approx.f32 %0, %1;" : "=f"(r) : "f"(x)); return r;
}
__device__ __forceinline__ float softmin3s(float a, float b, float c) {
    float mn = fminf(fminf(a, b), c);
    float s  = ex2f(mn - a) + ex2f(mn - b) + ex2f(mn - c);
    return mn - lg2f(s);
}

// dynamic smem layout (bytes)
#define OFF_SY    0        // ulonglong2[8][256]  y chunk-transposed        32768
#define OFF_SYN   32768    // float[256] |y_j|^2 * LOG2E (reused for red)    1024
#define OFF_RING  33792    // [4 cons][RING slots][32 lanes x 8B fp16x4]    65536
#define OFF_PROG  99328    // int[4] producer progress + pad                   64
#define OFF_WRNG  99392    // u64[3][NBLK][2] dp handoff (tagged)            6144
#define OFF_CONS  105536   // int[4] consumer progress + pad                   64
#define SMEM_BYTES 105600
#define RING_C    16384    // per-consumer ring bytes (RING*256)

__global__ void __launch_bounds__(TPB, 2)
sdtw_kernel(const float* __restrict__ X, const float* __restrict__ Y,
            float* __restrict__ out) {
    extern __shared__ unsigned char sm[];
    ulonglong2*    sy16 = (ulonglong2*)(sm + OFF_SY);
    float*         syn  = (float*)(sm + OFF_SYN);
    volatile int*  cons = (volatile int*)(sm + OFF_CONS);
    __shared__ int islast;

    const int t    = threadIdx.x;
    const int lane = t & 31;
    const int wid  = t >> 5;
    const int b    = blockIdx.x;
    const float* xb = X + (size_t)b * NROWS * DDIM;
    const float* yb = Y + (size_t)b * MCOLS * DDIM;

    // ---- stage y chunk-transposed: sy16[c2][j] = float4 #c2 of y col j ----
    const ulonglong2* yb16 = (const ulonglong2*)yb;
    for (int k = t; k < MCOLS * 8; k += TPB) {
        int j = k >> 3, c2 = k & 7;
        sy16[c2 * 256 + j] = yb16[k];
    }
    {   // |y_j|^2 * LOG2E (pre-scaled)
        const float4* row = (const float4*)(yb + t * DDIM);
        float acc = 0.f;
        #pragma unroll
        for (int c = 0; c < 8; c++) {
            float4 v = row[c];
            acc += v.x * v.x + v.y * v.y + v.z * v.z + v.w * v.w;
        }
        syn[t] = acc * LOG2E;
    }
    for (int k = t; k < 3 * NBLK * 2; k += TPB) ((u64*)(sm + OFF_WRNG))[k] = 0ull;
    if (t < 4) { ((int*)(sm + OFF_PROG))[t] = 0; ((int*)(sm + OFF_CONS))[t] = 0; }

    // producers pre-load their 2 x rows, packed f32x2; norms pre-scaled
    u64 ax0[16], ax1[16];
    float xx0 = 0.f, xx1 = 0.f;
    if (wid < 4) {
        const ulonglong2* r0 = (const ulonglong2*)(xb + (size_t)(64 * wid + 2 * lane)     * DDIM);
        const ulonglong2* r1 = (const ulonglong2*)(xb + (size_t)(64 * wid + 2 * lane + 1) * DDIM);
        #pragma unroll
        for (int c2 = 0; c2 < 8; c2++) {
            ulonglong2 v0 = r0[c2], v1 = r1[c2];
            ax0[2*c2] = v0.x; ax0[2*c2+1] = v0.y;
            ax1[2*c2] = v1.x; ax1[2*c2+1] = v1.y;
            float a, bb;
            UNPACK_F32X2(a, bb, v0.x); xx0 += a*a + bb*bb;
            UNPACK_F32X2(a, bb, v0.y); xx0 += a*a + bb*bb;
            UNPACK_F32X2(a, bb, v1.x); xx1 += a*a + bb*bb;
            UNPACK_F32X2(a, bb, v1.y); xx1 += a*a + bb*bb;
        }
        xx0 *= LOG2E; xx1 *= LOG2E;
    }
    __syncthreads();

    if (wid < 4) {
        // ====== PRODUCER warp p: rows 64p+2l, +1; 2 cols/block; fp16 ring ======
        const int p = wid;
        unsigned rbase;
        {   void* gp = (void*)(sm + OFF_RING + p * RING_C + lane * 8);
            rbase = (unsigned)__cvta_generic_to_shared(gp); }
        unsigned paddr;
        {   void* gp = (void*)(sm + OFF_PROG + p * 4);
            paddr = (unsigned)__cvta_generic_to_shared(gp); }
        volatile int* myc = cons + p;
        int slot = 0;
        #pragma unroll 1
        for (int j = 0; j < NBLK; j++) {
            if (j >= SLACKCAP) {                    // backpressure (30+ blocks slack)
                while (*myc < j - SLACKCAP) {}
            }
            const int c0 = 2 * j;
            u64 a00 = 0ull, a10 = 0ull, a01 = 0ull, a11 = 0ull;
            #pragma unroll
            for (int c2 = 0; c2 < 8; c2++) {
                ulonglong2 y0 = sy16[c2 * 256 + c0];       // broadcast LDS.128
                ulonglong2 y1 = sy16[c2 * 256 + c0 + 1];
                FMA_F32X2(a00, ax0[2*c2], y0.x); FMA_F32X2(a00, ax0[2*c2+1], y0.y);
                FMA_F32X2(a10, ax1[2*c2], y0.x); FMA_F32X2(a10, ax1[2*c2+1], y0.y);
                FMA_F32X2(a01, ax0[2*c2], y1.x); FMA_F32X2(a01, ax0[2*c2+1], y1.y);
                FMA_F32X2(a11, ax1[2*c2], y1.x); FMA_F32X2(a11, ax1[2*c2+1], y1.y);
            }
            float lo, hi;
            UNPACK_F32X2(lo, hi, a00); float d00 = lo + hi;
            UNPACK_F32X2(lo, hi, a10); float d10 = lo + hi;
            UNPACK_F32X2(lo, hi, a01); float d01 = lo + hi;
            UNPACK_F32X2(lo, hi, a11); float d11 = lo + hi;
            float yn0 = syn[c0], yn1 = syn[c0 + 1];        // pre-scaled
            d00 = fmaxf(fmaf(d00, NEG2L, xx0 + yn0), 0.f);
            d10 = fmaxf(fmaf(d10, NEG2L, xx1 + yn0), 0.f);
            d01 = fmaxf(fmaf(d01, NEG2L, xx0 + yn1), 0.f);
            d11 = fmaxf(fmaf(d11, NEG2L, xx1 + yn1), 0.f);
            // fp16 pack: (r0c0, r1c0) | (r0c1, r1c1)
            __half2 h0 = __float22half2_rn(make_float2(d00, d10));
            __half2 h1 = __float22half2_rn(make_float2(d01, d11));
            unsigned u0 = *(unsigned*)&h0, u1 = *(unsigned*)&h1;
            unsigned a = rbase + (unsigned)(slot * 256);
            asm volatile("st.volatile.shared.v2.u32 [%0], {%1, %2};"
                         :: "r"(a), "r"(u0), "r"(u1));
            __syncwarp();
            if (lane == 0)
                asm volatile("st.volatile.shared.s32 [%0], %1;" :: "r"(paddr), "r"(j + 1));
            slot = (slot + 1) & (RING - 1);
        }
    } else {
        // ====== CONSUMER warp c: DP rows 64c+2l, +1; 2x2 tiles ======
        const int c = wid - 4;
        unsigned rbase;
        {   void* gp = (void*)(sm + OFF_RING + c * RING_C + lane * 8);
            rbase = (unsigned)__cvta_generic_to_shared(gp); }
        volatile int* myprog = (volatile int*)(sm + OFF_PROG) + c;
        unsigned caddr;
        {   void* gp = (void*)(sm + OFF_CONS + c * 4);
            caddr = (unsigned)__cvta_generic_to_shared(gp); }
        u64* wrng = (u64*)(sm + OFF_WRNG);
        volatile u64* myw = wrng + (size_t)c * NBLK * 2;        // if c<3
        unsigned upbase = 0;
        if (c > 0) {
            void* gp = (void*)(wrng + (size_t)(c - 1) * NBLK * 2);
            upbase = (unsigned)__cvta_generic_to_shared(gp);
        }

        float left0 = BIGF, left1 = BIGF;
        float tl = (c == 0 && lane == 0) ? 0.f : BIGF;
        float pv10 = BIGF, pv11 = BIGF;
        int slot = (RING - lane) & (RING - 1);      // slot of bk = i - lane

        #pragma unroll 1
        for (int i = 0; i < CITER; i++) {
            float s10 = __shfl_up_sync(0xffffffffu, pv10, 1);
            float s11 = __shfl_up_sync(0xffffffffu, pv11, 1);

            {   // producer ready (first-try hit: 30+ blocks of slack)
                const int need = (i + 1 < NBLK) ? i + 1 : NBLK;
                while (*myprog < need) {}
            }

            // own dist tile for block bk = i - lane (4 fp16 in one LDS.64)
            unsigned a = rbase + (unsigned)(slot * 256);
            unsigned u0, u1;
            asm volatile("ld.volatile.shared.v2.u32 {%0, %1}, [%2];"
                         : "=r"(u0), "=r"(u1) : "r"(a));
            float2 f0 = __half22float2(*(__half2*)&u0);    // (d r0c0, d r1c0)
            float2 f1 = __half22float2(*(__half2*)&u1);    // (d r0c1, d r1c1)

            // cross-warp up pair: all lanes read + uniform spin, SEL into lane 0
            float up0 = BIGF, up1 = BIGF;
            if (c > 0) {
                const int ii = (i < NBLK) ? i : (NBLK - 1);
                const unsigned tag = (unsigned)(ii + 1);
                unsigned ua = upbase + (unsigned)(ii * 16);
                u64 w0, w1;
                asm volatile("ld.volatile.shared.v2.u64 {%0, %1}, [%2];"
                             : "=l"(w0), "=l"(w1) : "r"(ua));
                while ((unsigned)(w0 >> 32) != tag || (unsigned)(w1 >> 32) != tag) {
                    asm volatile("ld.volatile.shared.v2.u64 {%0, %1}, [%2];"
                                 : "=l"(w0), "=l"(w1) : "r"(ua));
                }
                up0 = __uint_as_float((unsigned)w0);
                up1 = __uint_as_float((unsigned)w1);
            }
            up0 = (lane == 0) ? up0 : s10;
            up1 = (lane == 0) ? up1 : s11;

            // 2x2 cell tile, chain depth 3 (verified routing: v10<-r1c0, v01<-r0c1)
            float v00 = f0.x + softmin3s(up0, left0, tl);
            float v10 = f0.y + softmin3s(v00, left1, left0);
            float v01 = f1.x + softmin3s(up1, v00,   up0);
            float v11 = f1.y + softmin3s(v01, v10,   v00);

            const int bk = i - lane;
            const bool act = (bk >= 0) && (bk < NBLK);
            tl    = act ? up1 : tl;
            left0 = act ? v01 : left0;
            left1 = act ? v11 : left1;
            pv10  = act ? v10 : pv10;
            pv11  = act ? v11 : pv11;

            if (lane == 31) {                       // single divergent region
                int cv = i - 30;                    // free ring slots
                asm volatile("st.volatile.shared.s32 [%0], %1;"
                             :: "r"(caddr), "r"(cv));
                if (act && c < 3) {
                    u64 tw = (u64)(unsigned)(bk + 1) << 32;
                    myw[bk * 2 + 0] = tw | (u64)__float_as_uint(v10);
                    myw[bk * 2 + 1] = tw | (u64)__float_as_uint(v11);
                }
                if (c == 3 && bk == NBLK - 1)
                    g_part[b] = v11;                // scaled D[N][M]
            }

            slot = (slot + 1) & (RING - 1);
        }
    }

    // ---- fused grid reduction (last CTA); reuse syn[] as scratch ----
    __threadfence();
    __syncthreads();
    if (t == 0) islast = (atomicAdd(&g_count, 1) == BATCH - 1);
    __syncthreads();
    if (islast) {
        __threadfence();
        float* red = syn;
        red[t] = g_part[t];
        __syncthreads();
        #pragma unroll
        for (int off = TPB / 2; off > 0; off >>= 1) {
            if (t < off) red[t] += red[t + off];
            __syncthreads();
        }
        if (t == 0) {
            out[0] = red[0] * (1.0f / ((float)BATCH * LOG2E));
            g_count = 0;                            // reset for next graph replay
        }
    }
}

extern "C" void kernel_launch(void* const* d_in, const int* in_sizes, int n_in,
                              void* d_out, int out_size) {
    const float* x = (const float*)d_in[0];
    const float* y = (const float*)d_in[1];
    float* out = (float*)d_out;
    cudaFuncSetAttribute(sdtw_kernel, cudaFuncAttributeMaxDynamicSharedMemorySize,
                         SMEM_BYTES);
    sdtw_kernel<<<BATCH, TPB, SMEM_BYTES>>>(x, y, out);
}